// round 11
// baseline (speedup 1.0000x reference)
#include <cuda_runtime.h>

typedef unsigned long long ull;

#define THREADS 512
#define SMEM_FLOATS 57344             // dup table: 3 quad arrays + 1 pair array
#define SMEM_BYTES  (SMEM_FLOATS * 4) // 229376 B (staging reuses this after mainloop)

__device__ __forceinline__ ull pack2(float lo, float hi) {
    ull r; asm("mov.b64 %0, {%1, %2};" : "=l"(r) : "f"(lo), "f"(hi)); return r;
}
__device__ __forceinline__ void unpack2(ull v, float& lo, float& hi) {
    asm("mov.b64 {%0, %1}, %2;" : "=f"(lo), "=f"(hi) : "l"(v));
}
__device__ __forceinline__ ull mul2(ull a, ull b) {
    ull d; asm("mul.rn.f32x2 %0, %1, %2;" : "=l"(d) : "l"(a), "l"(b)); return d;
}
__device__ __forceinline__ ull fma2(ull a, ull b, ull c) {
    ull d; asm("fma.rn.f32x2 %0, %1, %2, %3;" : "=l"(d) : "l"(a), "l"(b), "l"(c)); return d;
}

// Compute one membership level for 4 elements into a (local-memory) pair
// array. The t-loop is rolled and the stores are pointer/dynamic-indexed so
// ptxas CANNOT promote LP/LQ into registers (this was the R9/R10 spill bug).
__device__ __forceinline__ void memb_level(
    const float* __restrict__ x, const float* __restrict__ centers,
    const float* __restrict__ sigmas, int i,
    int b0, int b1, int b2, int b3,
    ull* LP, ull* LQ,
    float& den0, float& den1, float& den2, float& den3)
{
    float x0 = x[b0 * 6 + i];
    float x1 = x[b1 * 6 + i];
    float x2 = x[b2 * 6 + i];
    float x3 = x[b3 * 6 + i];
    float s0 = 0.0f, s1 = 0.0f, s2 = 0.0f, s3 = 0.0f;
#pragma unroll 1
    for (int t = 0; t < 4; t++) {
        float c   = centers[i * 4 + t];
        float sg  = fabsf(sigmas[i * 4 + t]) + 1e-6f;
        float inv = 0.5f / (sg * sg);
        float e0 = x0 - c, e1 = x1 - c, e2 = x2 - c, e3 = x3 - c;
        float v0 = __expf(-e0 * e0 * inv);
        float v1 = __expf(-e1 * e1 * inv);
        float v2 = __expf(-e2 * e2 * inv);
        float v3 = __expf(-e3 * e3 * inv);
        s0 += v0; s1 += v1; s2 += v2; s3 += v3;
        LP[t] = pack2(v0, v1);
        LQ[t] = pack2(v2, v3);
    }
    den0 *= s0; den1 *= s1; den2 *= s2; den3 *= s3;
}

// ANFIS:
//   den[b] = prod_i (sum_t mu[b,i,t])
//   G[b,j] = sum_r w[b,r] * C[r,j]  (hierarchical base-4 partial products)
//   out[b] = (sum_j xa[b,j] * G[b,j]) / (den[b] + 1e-8)
// f32x2 packs ELEMENT PAIRS (P=(b0,b1), Q=(b2,b3); 4 elements/thread).
// Coefficients PRE-DUPLICATED in smem -> every LDS yields ready f32x2
// operands, zero duplication MOVs. Membership levels 0..4 live in LOCAL
// memory (rolled loops, dynamic indices); only level 5 + accumulators +
// the active A-chain stay in registers (~94 regs -> no spills).
// 16 warps/block = 8 rule-octants (fixed d0, half of d1) x 2 quad-groups.
// Octant partials are combined by REUSING the table smem after the mainloop.
__global__ void __launch_bounds__(THREADS, 1) anfis_kernel(
    const float* __restrict__ x,
    const float* __restrict__ centers,
    const float* __restrict__ sigmas,
    const float* __restrict__ cons,
    float* __restrict__ out)
{
    extern __shared__ float sm[];

    // --- Build duplicated table ---
    for (int idx = threadIdx.x; idx < 4096 * 7; idx += THREADS) {
        int r = idx / 7;
        int j = idx - r * 7;
        float v = cons[idx];
        float* dst;
        if (j < 6) dst = sm + ((j >> 1) << 14) + r * 4 + ((j & 1) << 1);
        else       dst = sm + 49152 + r * 2;
        dst[0] = v;
        dst[1] = v;
    }

    int lane = threadIdx.x & 31;
    int warp = threadIdx.x >> 5;
    int g    = warp & 1;            // quad group
    int rs   = warp >> 1;           // rule octant 0..7
    int d0   = rs >> 1;
    int d1h  = rs & 1;
    int quad = g * 32 + lane;       // 0..63
    int q    = blockIdx.x * 64 + quad;

    int b0 = q, b1 = q + 8192, b2 = q + 16384, b3 = q + 24576;

    // --- Memberships: levels 0-4 in local arrays, level 5 in registers ---
    ull l0P[4], l0Q[4], l1P[4], l1Q[4], l2P[4], l2Q[4];
    ull l3P[4], l3Q[4], l4P[4], l4Q[4];
    ull m5P[4], m5Q[4];
    float den0 = 1.0f, den1 = 1.0f, den2 = 1.0f, den3 = 1.0f;

    memb_level(x, centers, sigmas, 0, b0, b1, b2, b3, l0P, l0Q, den0, den1, den2, den3);
    memb_level(x, centers, sigmas, 1, b0, b1, b2, b3, l1P, l1Q, den0, den1, den2, den3);
    memb_level(x, centers, sigmas, 2, b0, b1, b2, b3, l2P, l2Q, den0, den1, den2, den3);
    memb_level(x, centers, sigmas, 3, b0, b1, b2, b3, l3P, l3Q, den0, den1, den2, den3);
    memb_level(x, centers, sigmas, 4, b0, b1, b2, b3, l4P, l4Q, den0, den1, den2, den3);
    {   // level 5 -> registers (unrolled, static indices)
        float x0 = x[b0 * 6 + 5];
        float x1 = x[b1 * 6 + 5];
        float x2 = x[b2 * 6 + 5];
        float x3 = x[b3 * 6 + 5];
        float s0 = 0.0f, s1 = 0.0f, s2 = 0.0f, s3 = 0.0f;
#pragma unroll
        for (int t = 0; t < 4; t++) {
            float c   = centers[5 * 4 + t];
            float sg  = fabsf(sigmas[5 * 4 + t]) + 1e-6f;
            float inv = 0.5f / (sg * sg);
            float e0 = x0 - c, e1 = x1 - c, e2 = x2 - c, e3 = x3 - c;
            float v0 = __expf(-e0 * e0 * inv);
            float v1 = __expf(-e1 * e1 * inv);
            float v2 = __expf(-e2 * e2 * inv);
            float v3 = __expf(-e3 * e3 * inv);
            s0 += v0; s1 += v1; s2 += v2; s3 += v3;
            m5P[t] = pack2(v0, v1);
            m5Q[t] = pack2(v2, v3);
        }
        den0 *= s0; den1 *= s1; den2 *= s2; den3 *= s3;
    }

    ull A0P = l0P[d0];
    ull A0Q = l0Q[d0];
    __syncthreads();

    const ulonglong2* Q0 = (const ulonglong2*)(sm);
    const ulonglong2* Q1 = (const ulonglong2*)(sm + 16384);
    const ulonglong2* Q2 = (const ulonglong2*)(sm + 32768);
    const ull*        P6 = (const ull*)(sm + 49152);

    ull accP[7], accQ[7];
#pragma unroll
    for (int j = 0; j < 7; j++) { accP[j] = 0; accQ[j] = 0; }

#pragma unroll 1
    for (int d1i = 0; d1i < 2; d1i++) {
        int d1 = d1h * 2 + d1i;
        ull A1P = mul2(A0P, l1P[d1]);
        ull A1Q = mul2(A0Q, l1Q[d1]);
#pragma unroll 1
        for (int d2 = 0; d2 < 4; d2++) {
            ull A2P = mul2(A1P, l2P[d2]);
            ull A2Q = mul2(A1Q, l2Q[d2]);
#pragma unroll 1
            for (int d3 = 0; d3 < 4; d3++) {
                ull A3P = mul2(A2P, l3P[d3]);
                ull A3Q = mul2(A2Q, l3Q[d3]);
                int rbase = d0 * 1024 + d1 * 256 + d2 * 64 + d3 * 16;
#pragma unroll 1
                for (int d4 = 0; d4 < 4; d4++) {
                    ull A4P = mul2(A3P, l4P[d4]);
                    ull A4Q = mul2(A3Q, l4Q[d4]);
                    int r = rbase + d4 * 4;
#pragma unroll
                    for (int d5 = 0; d5 < 4; d5++) {
                        ull wP = mul2(A4P, m5P[d5]);
                        ull wQ = mul2(A4Q, m5Q[d5]);
                        ulonglong2 q0 = Q0[r + d5];
                        ulonglong2 q1 = Q1[r + d5];
                        ulonglong2 q2 = Q2[r + d5];
                        ull        p6 = P6[r + d5];
                        accP[0] = fma2(wP, q0.x, accP[0]);
                        accQ[0] = fma2(wQ, q0.x, accQ[0]);
                        accP[1] = fma2(wP, q0.y, accP[1]);
                        accQ[1] = fma2(wQ, q0.y, accQ[1]);
                        accP[2] = fma2(wP, q1.x, accP[2]);
                        accQ[2] = fma2(wQ, q1.x, accQ[2]);
                        accP[3] = fma2(wP, q1.y, accP[3]);
                        accQ[3] = fma2(wQ, q1.y, accQ[3]);
                        accP[4] = fma2(wP, q2.x, accP[4]);
                        accQ[4] = fma2(wQ, q2.x, accQ[4]);
                        accP[5] = fma2(wP, q2.y, accP[5]);
                        accQ[5] = fma2(wQ, q2.y, accQ[5]);
                        accP[6] = fma2(wP, p6, accP[6]);
                        accQ[6] = fma2(wQ, p6, accQ[6]);
                    }
                }
            }
        }
    }

    // --- Octant combine: REUSE table smem as staging (all reads are done) ---
    __syncthreads();
    if (rs != 0) {
        float* base = sm + ((rs - 1) * 64 + quad) * 29;
#pragma unroll
        for (int j = 0; j < 7; j++) {
            float a, bf, c2, d2v;
            unpack2(accP[j], a, bf);
            unpack2(accQ[j], c2, d2v);
            base[j * 4 + 0] = a;
            base[j * 4 + 1] = bf;
            base[j * 4 + 2] = c2;
            base[j * 4 + 3] = d2v;
        }
    }
    __syncthreads();

    if (rs == 0) {
        float g0[7], g1[7], g2[7], g3[7];
#pragma unroll
        for (int j = 0; j < 7; j++) {
            unpack2(accP[j], g0[j], g1[j]);
            unpack2(accQ[j], g2[j], g3[j]);
        }
#pragma unroll 1
        for (int o = 0; o < 7; o++) {
            const float* base = sm + (o * 64 + quad) * 29;
#pragma unroll
            for (int j = 0; j < 7; j++) {
                g0[j] += base[j * 4 + 0];
                g1[j] += base[j * 4 + 1];
                g2[j] += base[j * 4 + 2];
                g3[j] += base[j * 4 + 3];
            }
        }
        float n0 = g0[6], n1 = g1[6], n2 = g2[6], n3 = g3[6];
#pragma unroll
        for (int i = 0; i < 6; i++) {
            n0 += g0[i] * x[b0 * 6 + i];
            n1 += g1[i] * x[b1 * 6 + i];
            n2 += g2[i] * x[b2 * 6 + i];
            n3 += g3[i] * x[b3 * 6 + i];
        }
        out[b0] = n0 / (den0 + 1e-8f);
        out[b1] = n1 / (den1 + 1e-8f);
        out[b2] = n2 / (den2 + 1e-8f);
        out[b3] = n3 / (den3 + 1e-8f);
    }
}

extern "C" void kernel_launch(void* const* d_in, const int* in_sizes, int n_in,
                              void* d_out, int out_size) {
    const float* x       = (const float*)d_in[0];
    const float* centers = (const float*)d_in[1];
    const float* sigmas  = (const float*)d_in[2];
    const float* cons    = (const float*)d_in[3];
    float* out = (float*)d_out;

    int B = in_sizes[0] / 6;        // 32768
    int blocks = B / 256;           // 128 (64 quads x 4 elements)

    cudaFuncSetAttribute(anfis_kernel,
                         cudaFuncAttributeMaxDynamicSharedMemorySize, SMEM_BYTES);

    anfis_kernel<<<blocks, THREADS, SMEM_BYTES>>>(x, centers, sigmas, cons, out);
}

// round 12
// speedup vs baseline: 1.1541x; 1.1541x over previous
#include <cuda_runtime.h>

typedef unsigned long long ull;

#define THREADS 512
#define SMEM_FLOATS 57344             // dup table: 3 quad arrays + 1 pair array
#define SMEM_BYTES  (SMEM_FLOATS * 4) // 229376 B (staging reuses this after mainloop)

__device__ __forceinline__ ull pack2(float lo, float hi) {
    ull r; asm("mov.b64 %0, {%1, %2};" : "=l"(r) : "f"(lo), "f"(hi)); return r;
}
__device__ __forceinline__ void unpack2(ull v, float& lo, float& hi) {
    asm("mov.b64 {%0, %1}, %2;" : "=f"(lo), "=f"(hi) : "l"(v));
}
__device__ __forceinline__ ull mul2(ull a, ull b) {
    ull d; asm("mul.rn.f32x2 %0, %1, %2;" : "=l"(d) : "l"(a), "l"(b)); return d;
}
__device__ __forceinline__ ull fma2(ull a, ull b, ull c) {
    ull d; asm("fma.rn.f32x2 %0, %1, %2, %3;" : "=l"(d) : "l"(a), "l"(b), "l"(c)); return d;
}

// One membership level for 4 elements into LOCAL-memory pair arrays.
// Rolled t-loop + pointer stores prevent ptxas register promotion.
__device__ __forceinline__ void memb_level(
    const float* __restrict__ x, const float* __restrict__ centers,
    const float* __restrict__ sigmas, int i,
    int b0, int b1, int b2, int b3,
    ull* LP, ull* LQ,
    float& den0, float& den1, float& den2, float& den3)
{
    float x0 = x[b0 * 6 + i];
    float x1 = x[b1 * 6 + i];
    float x2 = x[b2 * 6 + i];
    float x3 = x[b3 * 6 + i];
    float s0 = 0.0f, s1 = 0.0f, s2 = 0.0f, s3 = 0.0f;
#pragma unroll 1
    for (int t = 0; t < 4; t++) {
        float c   = centers[i * 4 + t];
        float sg  = fabsf(sigmas[i * 4 + t]) + 1e-6f;
        float inv = 0.5f / (sg * sg);
        float e0 = x0 - c, e1 = x1 - c, e2 = x2 - c, e3 = x3 - c;
        float v0 = __expf(-e0 * e0 * inv);
        float v1 = __expf(-e1 * e1 * inv);
        float v2 = __expf(-e2 * e2 * inv);
        float v3 = __expf(-e3 * e3 * inv);
        s0 += v0; s1 += v1; s2 += v2; s3 += v3;
        LP[t] = pack2(v0, v1);
        LQ[t] = pack2(v2, v3);
    }
    den0 *= s0; den1 *= s1; den2 *= s2; den3 *= s3;
}

// ANFIS:
//   den[b] = prod_i (sum_t mu[b,i,t])
//   G[b,j] = sum_r w[b,r] * C[r,j]  (hierarchical base-4 partial products)
//   out[b] = (sum_j xa[b,j] * G[b,j]) / (den[b] + 1e-8)
// f32x2 packs ELEMENT PAIRS (P=(b0,b1), Q=(b2,b3); 4 elements/thread).
// Coefficients PRE-DUPLICATED in smem -> every LDS yields ready f32x2
// operands, zero duplication MOVs.
// Register discipline (lesson of R9/R10/R11):
//   levels 0-3 -> LOCAL memory, read only at d1/d2/d3 loop levels
//   levels 4-5 -> REGISTERS, d4*d5 fully unrolled (16-rule block,
//                 64 batched LDS, no LDL inside)
// 16 warps/block = 8 rule-octants (fixed d0, half of d1) x 2 quad-groups.
// Octant partials combined by REUSING the table smem after the mainloop.
__global__ void __launch_bounds__(THREADS, 1) anfis_kernel(
    const float* __restrict__ x,
    const float* __restrict__ centers,
    const float* __restrict__ sigmas,
    const float* __restrict__ cons,
    float* __restrict__ out)
{
    extern __shared__ float sm[];

    // --- Build duplicated table ---
    for (int idx = threadIdx.x; idx < 4096 * 7; idx += THREADS) {
        int r = idx / 7;
        int j = idx - r * 7;
        float v = cons[idx];
        float* dst;
        if (j < 6) dst = sm + ((j >> 1) << 14) + r * 4 + ((j & 1) << 1);
        else       dst = sm + 49152 + r * 2;
        dst[0] = v;
        dst[1] = v;
    }

    int lane = threadIdx.x & 31;
    int warp = threadIdx.x >> 5;
    int g    = warp & 1;            // quad group
    int rs   = warp >> 1;           // rule octant 0..7
    int d0   = rs >> 1;
    int d1h  = rs & 1;
    int quad = g * 32 + lane;       // 0..63
    int q    = blockIdx.x * 64 + quad;

    int b0 = q, b1 = q + 8192, b2 = q + 16384, b3 = q + 24576;

    // --- Memberships: levels 0-3 local, levels 4-5 registers ---
    ull l0P[4], l0Q[4], l1P[4], l1Q[4], l2P[4], l2Q[4], l3P[4], l3Q[4];
    ull m4P[4], m4Q[4], m5P[4], m5Q[4];
    float den0 = 1.0f, den1 = 1.0f, den2 = 1.0f, den3 = 1.0f;

    memb_level(x, centers, sigmas, 0, b0, b1, b2, b3, l0P, l0Q, den0, den1, den2, den3);
    memb_level(x, centers, sigmas, 1, b0, b1, b2, b3, l1P, l1Q, den0, den1, den2, den3);
    memb_level(x, centers, sigmas, 2, b0, b1, b2, b3, l2P, l2Q, den0, den1, den2, den3);
    memb_level(x, centers, sigmas, 3, b0, b1, b2, b3, l3P, l3Q, den0, den1, den2, den3);
#pragma unroll
    for (int i = 4; i < 6; i++) {   // levels 4,5 -> registers (static indices)
        float x0 = x[b0 * 6 + i];
        float x1 = x[b1 * 6 + i];
        float x2 = x[b2 * 6 + i];
        float x3 = x[b3 * 6 + i];
        float s0 = 0.0f, s1 = 0.0f, s2 = 0.0f, s3 = 0.0f;
#pragma unroll
        for (int t = 0; t < 4; t++) {
            float c   = centers[i * 4 + t];
            float sg  = fabsf(sigmas[i * 4 + t]) + 1e-6f;
            float inv = 0.5f / (sg * sg);
            float e0 = x0 - c, e1 = x1 - c, e2 = x2 - c, e3 = x3 - c;
            float v0 = __expf(-e0 * e0 * inv);
            float v1 = __expf(-e1 * e1 * inv);
            float v2 = __expf(-e2 * e2 * inv);
            float v3 = __expf(-e3 * e3 * inv);
            s0 += v0; s1 += v1; s2 += v2; s3 += v3;
            if (i == 4) { m4P[t] = pack2(v0, v1); m4Q[t] = pack2(v2, v3); }
            else        { m5P[t] = pack2(v0, v1); m5Q[t] = pack2(v2, v3); }
        }
        den0 *= s0; den1 *= s1; den2 *= s2; den3 *= s3;
    }

    ull A0P = l0P[d0];
    ull A0Q = l0Q[d0];
    __syncthreads();

    const ulonglong2* Q0 = (const ulonglong2*)(sm);
    const ulonglong2* Q1 = (const ulonglong2*)(sm + 16384);
    const ulonglong2* Q2 = (const ulonglong2*)(sm + 32768);
    const ull*        P6 = (const ull*)(sm + 49152);

    ull accP[7], accQ[7];
#pragma unroll
    for (int j = 0; j < 7; j++) { accP[j] = 0; accQ[j] = 0; }

#pragma unroll 1
    for (int d1i = 0; d1i < 2; d1i++) {
        int d1 = d1h * 2 + d1i;
        ull A1P = mul2(A0P, l1P[d1]);
        ull A1Q = mul2(A0Q, l1Q[d1]);
#pragma unroll 1
        for (int d2 = 0; d2 < 4; d2++) {
            ull A2P = mul2(A1P, l2P[d2]);
            ull A2Q = mul2(A1Q, l2Q[d2]);
#pragma unroll 1
            for (int d3 = 0; d3 < 4; d3++) {
                ull A3P = mul2(A2P, l3P[d3]);
                ull A3Q = mul2(A2Q, l3Q[d3]);
                int rbase = d0 * 1024 + d1 * 256 + d2 * 64 + d3 * 16;
#pragma unroll
                for (int d4 = 0; d4 < 4; d4++) {
                    ull A4P = mul2(A3P, m4P[d4]);
                    ull A4Q = mul2(A3Q, m4Q[d4]);
                    int r = rbase + d4 * 4;
#pragma unroll
                    for (int d5 = 0; d5 < 4; d5++) {
                        ull wP = mul2(A4P, m5P[d5]);
                        ull wQ = mul2(A4Q, m5Q[d5]);
                        ulonglong2 q0 = Q0[r + d5];
                        ulonglong2 q1 = Q1[r + d5];
                        ulonglong2 q2 = Q2[r + d5];
                        ull        p6 = P6[r + d5];
                        accP[0] = fma2(wP, q0.x, accP[0]);
                        accQ[0] = fma2(wQ, q0.x, accQ[0]);
                        accP[1] = fma2(wP, q0.y, accP[1]);
                        accQ[1] = fma2(wQ, q0.y, accQ[1]);
                        accP[2] = fma2(wP, q1.x, accP[2]);
                        accQ[2] = fma2(wQ, q1.x, accQ[2]);
                        accP[3] = fma2(wP, q1.y, accP[3]);
                        accQ[3] = fma2(wQ, q1.y, accQ[3]);
                        accP[4] = fma2(wP, q2.x, accP[4]);
                        accQ[4] = fma2(wQ, q2.x, accQ[4]);
                        accP[5] = fma2(wP, q2.y, accP[5]);
                        accQ[5] = fma2(wQ, q2.y, accQ[5]);
                        accP[6] = fma2(wP, p6, accP[6]);
                        accQ[6] = fma2(wQ, p6, accQ[6]);
                    }
                }
            }
        }
    }

    // --- Octant combine: REUSE table smem as staging (all reads are done) ---
    __syncthreads();
    if (rs != 0) {
        float* base = sm + ((rs - 1) * 64 + quad) * 29;
#pragma unroll
        for (int j = 0; j < 7; j++) {
            float a, bf, c2, d2v;
            unpack2(accP[j], a, bf);
            unpack2(accQ[j], c2, d2v);
            base[j * 4 + 0] = a;
            base[j * 4 + 1] = bf;
            base[j * 4 + 2] = c2;
            base[j * 4 + 3] = d2v;
        }
    }
    __syncthreads();

    if (rs == 0) {
        float g0[7], g1[7], g2[7], g3[7];
#pragma unroll
        for (int j = 0; j < 7; j++) {
            unpack2(accP[j], g0[j], g1[j]);
            unpack2(accQ[j], g2[j], g3[j]);
        }
#pragma unroll 1
        for (int o = 0; o < 7; o++) {
            const float* base = sm + (o * 64 + quad) * 29;
#pragma unroll
            for (int j = 0; j < 7; j++) {
                g0[j] += base[j * 4 + 0];
                g1[j] += base[j * 4 + 1];
                g2[j] += base[j * 4 + 2];
                g3[j] += base[j * 4 + 3];
            }
        }
        float n0 = g0[6], n1 = g1[6], n2 = g2[6], n3 = g3[6];
#pragma unroll
        for (int i = 0; i < 6; i++) {
            n0 += g0[i] * x[b0 * 6 + i];
            n1 += g1[i] * x[b1 * 6 + i];
            n2 += g2[i] * x[b2 * 6 + i];
            n3 += g3[i] * x[b3 * 6 + i];
        }
        out[b0] = n0 / (den0 + 1e-8f);
        out[b1] = n1 / (den1 + 1e-8f);
        out[b2] = n2 / (den2 + 1e-8f);
        out[b3] = n3 / (den3 + 1e-8f);
    }
}

extern "C" void kernel_launch(void* const* d_in, const int* in_sizes, int n_in,
                              void* d_out, int out_size) {
    const float* x       = (const float*)d_in[0];
    const float* centers = (const float*)d_in[1];
    const float* sigmas  = (const float*)d_in[2];
    const float* cons    = (const float*)d_in[3];
    float* out = (float*)d_out;

    int B = in_sizes[0] / 6;        // 32768
    int blocks = B / 256;           // 128 (64 quads x 4 elements)

    cudaFuncSetAttribute(anfis_kernel,
                         cudaFuncAttributeMaxDynamicSharedMemorySize, SMEM_BYTES);

    anfis_kernel<<<blocks, THREADS, SMEM_BYTES>>>(x, centers, sigmas, cons, out);
}

// round 13
// speedup vs baseline: 1.1916x; 1.0325x over previous
#include <cuda_runtime.h>

typedef unsigned long long ull;

#define THREADS 512
#define TABLE_FLOATS (7 * 4096)               // j-major coefficient table (112 KB)
#define RED_FLOATS   (3 * 128 * 15)           // 3 quarters x 128 slots x 15 (pad)
#define SMEM_BYTES   ((TABLE_FLOATS + RED_FLOATS) * 4)   // 137728 B

__device__ __forceinline__ ull pack2(float lo, float hi) {
    ull r; asm("mov.b64 %0, {%1, %2};" : "=l"(r) : "f"(lo), "f"(hi)); return r;
}
__device__ __forceinline__ void unpack2(ull v, float& lo, float& hi) {
    asm("mov.b64 {%0, %1}, %2;" : "=f"(lo), "=f"(hi) : "l"(v));
}
__device__ __forceinline__ ull mul2(ull a, ull b) {
    ull d; asm("mul.rn.f32x2 %0, %1, %2;" : "=l"(d) : "l"(a), "l"(b)); return d;
}
__device__ __forceinline__ ull fma2(ull a, ull b, ull c) {
    ull d; asm("fma.rn.f32x2 %0, %1, %2, %3;" : "=l"(d) : "l"(a), "l"(b), "l"(c)); return d;
}

// One membership level for 2 elements into LOCAL-memory DUPLICATED-pair
// arrays. Rolled t-loop + pointer stores prevent ptxas register promotion.
__device__ __forceinline__ void memb_level(
    const float* __restrict__ x, const float* __restrict__ centers,
    const float* __restrict__ sigmas, int i,
    int b0, int b1, ull* L0, ull* L1, float& den0, float& den1)
{
    float x0 = x[b0 * 6 + i];
    float x1 = x[b1 * 6 + i];
    float s0 = 0.0f, s1 = 0.0f;
#pragma unroll 1
    for (int t = 0; t < 4; t++) {
        float c   = centers[i * 4 + t];
        float sg  = fabsf(sigmas[i * 4 + t]) + 1e-6f;
        float inv = 0.5f / (sg * sg);
        float e0 = x0 - c, e1 = x1 - c;
        float v0 = __expf(-e0 * e0 * inv);
        float v1 = __expf(-e1 * e1 * inv);
        s0 += v0; s1 += v1;
        L0[t] = pack2(v0, v0);
        L1[t] = pack2(v1, v1);
    }
    den0 *= s0; den1 *= s1;
}

// ANFIS:
//   den[b] = prod_i (sum_t mu[b,i,t])
//   G[b,j] = sum_r w[b,r] * C[r,j]  (hierarchical base-4 partial products)
//   out[b] = (sum_j xa[b,j] * G[b,j]) / (den[b] + 1e-8)
// f32x2 packs RULE PAIRS: each float4 from the j-major table provides two
// ready operands (c.x,c.y) and (c.z,c.w) -> ZERO duplication MOVs, only
// 7 LDS per 4-rule body. Each thread carries 2 elements scalar-wise; the
// w-chain uses duplicated membership pairs, level-5 natural pairs.
// Register diet: levels 0-3 in LOCAL memory (reads at d1/d2/d3 levels),
// level-4 dup + level-5 pairs + 14 accumulators in registers (~100 regs),
// leaving ptxas slack to pipeline the 28-LDS d3 block.
// 16 warps/block = 4 rule-quarters (fixed d0) x 4 element-warps.
// Quarter partials combined via a dedicated smem staging buffer.
__global__ void __launch_bounds__(THREADS, 1) anfis_kernel(
    const float* __restrict__ x,
    const float* __restrict__ centers,
    const float* __restrict__ sigmas,
    const float* __restrict__ cons,
    float* __restrict__ out)
{
    extern __shared__ float sm[];
    float* red = sm + TABLE_FLOATS;

    // --- Build j-major table: sm[j*4096 + r] = cons[r*7 + j] ---
    for (int idx = threadIdx.x; idx < TABLE_FLOATS; idx += THREADS) {
        int j = idx >> 12;
        int r = idx & 4095;
        sm[idx] = cons[r * 7 + j];
    }

    int lane  = threadIdx.x & 31;
    int warp  = threadIdx.x >> 5;
    int qtr   = warp >> 2;              // 0..3: fixed level-0 digit d0
    int tslot = (warp & 3) * 32 + lane; // 0..127
    int b0    = blockIdx.x * 256 + tslot;
    int b1    = b0 + 128;

    // --- Memberships: levels 0-3 local (dup pairs), 4-5 registers ---
    ull l0_0[4], l0_1[4], l1_0[4], l1_1[4], l2_0[4], l2_1[4], l3_0[4], l3_1[4];
    ull m4_0[4], m4_1[4];
    ull p01_0, p23_0, p01_1, p23_1;
    float den0 = 1.0f, den1 = 1.0f;

    memb_level(x, centers, sigmas, 0, b0, b1, l0_0, l0_1, den0, den1);
    memb_level(x, centers, sigmas, 1, b0, b1, l1_0, l1_1, den0, den1);
    memb_level(x, centers, sigmas, 2, b0, b1, l2_0, l2_1, den0, den1);
    memb_level(x, centers, sigmas, 3, b0, b1, l3_0, l3_1, den0, den1);
    {   // level 4 -> duplicated register pairs
        float x0 = x[b0 * 6 + 4], x1 = x[b1 * 6 + 4];
        float s0 = 0.0f, s1 = 0.0f;
#pragma unroll
        for (int t = 0; t < 4; t++) {
            float c   = centers[4 * 4 + t];
            float sg  = fabsf(sigmas[4 * 4 + t]) + 1e-6f;
            float inv = 0.5f / (sg * sg);
            float e0 = x0 - c, e1 = x1 - c;
            float v0 = __expf(-e0 * e0 * inv);
            float v1 = __expf(-e1 * e1 * inv);
            s0 += v0; s1 += v1;
            m4_0[t] = pack2(v0, v0);
            m4_1[t] = pack2(v1, v1);
        }
        den0 *= s0; den1 *= s1;
    }
    {   // level 5 -> natural rule pairs
        float x0 = x[b0 * 6 + 5], x1 = x[b1 * 6 + 5];
        float v0[4], v1[4];
        float s0 = 0.0f, s1 = 0.0f;
#pragma unroll
        for (int t = 0; t < 4; t++) {
            float c   = centers[5 * 4 + t];
            float sg  = fabsf(sigmas[5 * 4 + t]) + 1e-6f;
            float inv = 0.5f / (sg * sg);
            float e0 = x0 - c, e1 = x1 - c;
            v0[t] = __expf(-e0 * e0 * inv);
            v1[t] = __expf(-e1 * e1 * inv);
            s0 += v0[t]; s1 += v1[t];
        }
        den0 *= s0; den1 *= s1;
        p01_0 = pack2(v0[0], v0[1]);
        p23_0 = pack2(v0[2], v0[3]);
        p01_1 = pack2(v1[0], v1[1]);
        p23_1 = pack2(v1[2], v1[3]);
    }

    ull A0_0 = l0_0[qtr];
    ull A0_1 = l0_1[qtr];
    __syncthreads();

    const float4* C4 = (const float4*)sm;   // C4[j*1024 + quadIdx]

    ull acc0[7], acc1[7];
#pragma unroll
    for (int j = 0; j < 7; j++) { acc0[j] = 0; acc1[j] = 0; }

#pragma unroll 1
    for (int d1 = 0; d1 < 4; d1++) {
        ull A1_0 = mul2(A0_0, l1_0[d1]);
        ull A1_1 = mul2(A0_1, l1_1[d1]);
#pragma unroll 1
        for (int d2 = 0; d2 < 4; d2++) {
            ull A2_0 = mul2(A1_0, l2_0[d2]);
            ull A2_1 = mul2(A1_1, l2_1[d2]);
#pragma unroll 1
            for (int d3 = 0; d3 < 4; d3++) {
                ull A3_0 = mul2(A2_0, l3_0[d3]);
                ull A3_1 = mul2(A2_1, l3_1[d3]);
                int qb = qtr * 256 + d1 * 64 + d2 * 16 + d3 * 4;
#pragma unroll
                for (int d4 = 0; d4 < 4; d4++) {
                    ull A4_0 = mul2(A3_0, m4_0[d4]);
                    ull A4_1 = mul2(A3_1, m4_1[d4]);
                    ull w01_0 = mul2(A4_0, p01_0);
                    ull w23_0 = mul2(A4_0, p23_0);
                    ull w01_1 = mul2(A4_1, p01_1);
                    ull w23_1 = mul2(A4_1, p23_1);
                    int qq = qb + d4;
#pragma unroll
                    for (int j = 0; j < 7; j++) {
                        float4 c = C4[j * 1024 + qq];
                        ull cA = pack2(c.x, c.y);   // consecutive regs: no MOV
                        ull cB = pack2(c.z, c.w);
                        acc0[j] = fma2(w01_0, cA, acc0[j]);
                        acc1[j] = fma2(w01_1, cA, acc1[j]);
                        acc0[j] = fma2(w23_0, cB, acc0[j]);
                        acc1[j] = fma2(w23_1, cB, acc1[j]);
                    }
                }
            }
        }
    }

    // --- Collapse rule pairs: g = lo + hi ---
    float g0[7], g1[7];
#pragma unroll
    for (int j = 0; j < 7; j++) {
        float lo, hi;
        unpack2(acc0[j], lo, hi); g0[j] = lo + hi;
        unpack2(acc1[j], lo, hi); g1[j] = lo + hi;
    }

    // --- Combine 4 rule-quarters via smem staging (stride 15: conflict-free) ---
    if (qtr != 0) {
        float* base = red + ((qtr - 1) * 128 + tslot) * 15;
#pragma unroll
        for (int j = 0; j < 7; j++) {
            base[j]     = g0[j];
            base[7 + j] = g1[j];
        }
    }
    __syncthreads();

    if (qtr == 0) {
#pragma unroll 1
        for (int o = 0; o < 3; o++) {
            const float* base = red + (o * 128 + tslot) * 15;
#pragma unroll
            for (int j = 0; j < 7; j++) {
                g0[j] += base[j];
                g1[j] += base[7 + j];
            }
        }
        float n0 = g0[6], n1 = g1[6];
#pragma unroll
        for (int i = 0; i < 6; i++) {
            n0 += g0[i] * x[b0 * 6 + i];
            n1 += g1[i] * x[b1 * 6 + i];
        }
        out[b0] = n0 / (den0 + 1e-8f);
        out[b1] = n1 / (den1 + 1e-8f);
    }
}

extern "C" void kernel_launch(void* const* d_in, const int* in_sizes, int n_in,
                              void* d_out, int out_size) {
    const float* x       = (const float*)d_in[0];
    const float* centers = (const float*)d_in[1];
    const float* sigmas  = (const float*)d_in[2];
    const float* cons    = (const float*)d_in[3];
    float* out = (float*)d_out;

    int B = in_sizes[0] / 6;        // 32768
    int blocks = B / 256;           // 128

    cudaFuncSetAttribute(anfis_kernel,
                         cudaFuncAttributeMaxDynamicSharedMemorySize, SMEM_BYTES);

    anfis_kernel<<<blocks, THREADS, SMEM_BYTES>>>(x, centers, sigmas, cons, out);
}